// round 1
// baseline (speedup 1.0000x reference)
#include <cuda_runtime.h>

// FernSparseTable: out[n,d,h,w] = bias[d] + sum_m sum_p AT[m,p,px] * weights[m][IT[m,p,px]][d]
//
// Design:
//  - gridDim = (256, 2): 256 pixel-chunks of 512 pixels, 2 D-halves (d in [0,32) or [32,64)).
//  - Each CTA (512 thr) keeps the current fern's half-table (1024x32 fp32 = 128 KB) in smem.
//  - Phase 1 (thread-per-pixel): fern logic -> 8 (smem byte offset, coefficient) pairs.
//  - Phase 2 (warp-per-pixel, lane-per-d): shfl-broadcast pairs, conflict-free LDS gathers,
//    FMA into 32 register accumulators per lane (pixel-major), held across all 16 ferns.
//  - Epilogue: smem transpose (reusing table region) -> fully coalesced STG.

#define TPB 512
#define PX_PER_CTA 512
#define SMEM_BYTES 131072  // 1024 * 32 floats

extern __shared__ float s_tab[];

__global__ __launch_bounds__(TPB, 1)
void fern_kernel(const float* __restrict__ B,
                 const float* __restrict__ W,
                 const float* __restrict__ bias,
                 float* __restrict__ out)
{
    const int tid   = threadIdx.x;
    const int lane  = tid & 31;
    const int warp  = tid >> 5;
    const int dhalf = blockIdx.y;            // 0 or 1
    const int pxbase = blockIdx.x * PX_PER_CTA;
    const int n      = pxbase >> 12;         // 4096 pixels per image; 512 | 4096
    const int hwbase = pxbase & 4095;
    const int my_hw  = hwbase + tid;

    const float* tab_lane = s_tab + lane;    // lane's d-column within a row
    const float* Bb = B + (n * 160) * 4096 + my_hw;

    float acc[32];
    #pragma unroll
    for (int p = 0; p < 32; ++p) acc[p] = 0.f;

    #pragma unroll 1
    for (int m = 0; m < 16; ++m) {
        __syncthreads();  // previous fern's gathers done before overwriting table
        // ---- load half-table: weights[m][:, dhalf*32 : dhalf*32+32] ----
        {
            const float4* wsrc = (const float4*)(W + m * 65536 + dhalf * 32);
            float4* dst = (float4*)s_tab;
            #pragma unroll
            for (int i = 0; i < 16; ++i) {
                int idx = tid + i * TPB;          // 0..8191 float4
                int r = idx >> 3, q = idx & 7;    // row, quad-within-half-row
                dst[idx] = wsrc[r * 16 + q];      // global row stride = 64 floats = 16 float4
            }
        }
        __syncthreads();

        // ---- phase 1: per-thread fern logic for its own pixel ----
        float t[10];
        #pragma unroll
        for (int k = 0; k < 10; ++k)
            t[k] = Bb[(m * 10 + k) * 4096];

        int wb = 0;
        float bsp = 1.f;
        float ba[10];
        #pragma unroll
        for (int k = 0; k < 10; ++k) {
            if (t[k] >= 0.5f) wb |= (1 << k);
            bsp *= fmaxf(t[k], 1.f - t[k]);
            ba[k] = fabsf(t[k] - 0.5f);
        }

        // three first-min argmins with exclusion (matches jnp.argmin + BA[a]+=1)
        int abi0, abi1, abi2;
        float av0, av1, av2;
        {
            float best = ba[0]; int bi = 0; float bt = t[0];
            #pragma unroll
            for (int k = 1; k < 10; ++k)
                if (ba[k] < best) { best = ba[k]; bi = k; bt = t[k]; }
            abi0 = bi; av0 = bt;
        }
        {
            float best = 3.0e38f; int bi = 0; float bt = 0.f;
            #pragma unroll
            for (int k = 0; k < 10; ++k)
                if (k != abi0 && ba[k] < best) { best = ba[k]; bi = k; bt = t[k]; }
            abi1 = bi; av1 = bt;
        }
        {
            float best = 3.0e38f; int bi = 0; float bt = 0.f;
            #pragma unroll
            for (int k = 0; k < 10; ++k)
                if (k != abi0 && k != abi1 && ba[k] < best) { best = ba[k]; bi = k; bt = t[k]; }
            abi2 = bi; av2 = bt;
        }

        const float d0 = 1.f - av0, d1 = 1.f - av1, d2 = 1.f - av2;
        const float denom = fmaxf(av0, d0) * fmaxf(av1, d1) * fmaxf(av2, d2);
        const float bspp = bsp / denom;

        float cp[8];
        {
            float g0 = bspp * d0,  g1 = bspp * av0;          // bit0
            float c00 = g0 * d1, c10 = g1 * d1;              // bit1 = 0
            float c01 = g0 * av1, c11 = g1 * av1;            // bit1 = 1
            cp[0] = c00 * d2;  cp[1] = c10 * d2;  cp[2] = c01 * d2;  cp[3] = c11 * d2;
            cp[4] = c00 * av2; cp[5] = c10 * av2; cp[6] = c01 * av2; cp[7] = c11 * av2;
        }
        int io[8];
        {
            const int m0 = 1 << abi0, m1 = 1 << abi1, m2 = 1 << abi2;
            const int b0 = wb & ~(m0 | m1 | m2);
            const int i0 = b0, i1 = b0 | m0, i2 = b0 | m1, i3 = b0 | m0 | m1;
            io[0] = i0 << 7;        io[1] = i1 << 7;        // byte offset: row * 32 floats * 4B
            io[2] = i2 << 7;        io[3] = i3 << 7;
            io[4] = (i0 | m2) << 7; io[5] = (i1 | m2) << 7;
            io[6] = (i2 | m2) << 7; io[7] = (i3 | m2) << 7;
        }

        // ---- phase 2: warp-per-pixel gathers, lane = d ----
        #pragma unroll
        for (int p = 0; p < 32; ++p) {
            float s = 0.f;
            #pragma unroll
            for (int j = 0; j < 8; ++j) {
                int   off = __shfl_sync(0xffffffffu, io[j], p);
                float c   = __shfl_sync(0xffffffffu, cp[j], p);
                float wv  = *(const float*)((const char*)tab_lane + off);
                s = fmaf(c, wv, s);
            }
            acc[p] += s;
        }
    }

    // ---- epilogue: transpose via smem (reuse table region), coalesced stores ----
    __syncthreads();
    float* buf = s_tab + warp * (32 * 33);
    #pragma unroll
    for (int p = 0; p < 32; ++p)
        buf[lane * 33 + p] = acc[p];     // bank (lane+p)%32: conflict-free
    __syncwarp();

    const int dbase = dhalf * 32;
    const int hw_warp = hwbase + warp * 32;
    const int out_n = n << 18;           // n * 64 * 4096
    #pragma unroll
    for (int i = 0; i < 32; ++i) {
        float v = buf[i * 33 + lane] + bias[dbase + i];
        out[out_n + ((dbase + i) << 12) + hw_warp + lane] = v;
    }
}

extern "C" void kernel_launch(void* const* d_in, const int* in_sizes, int n_in,
                              void* d_out, int out_size)
{
    const float* B    = (const float*)d_in[0];
    const float* W    = (const float*)d_in[1];
    const float* bias = (const float*)d_in[2];
    float* out = (float*)d_out;

    cudaFuncSetAttribute(fern_kernel, cudaFuncAttributeMaxDynamicSharedMemorySize, SMEM_BYTES);

    dim3 grid(256, 2);
    fern_kernel<<<grid, TPB, SMEM_BYTES>>>(B, W, bias, out);
}

// round 3
// speedup vs baseline: 2.7713x; 2.7713x over previous
#include <cuda_runtime.h>
#include <cuda_fp16.h>

// FernSparseTable v2:
//  - fp16 full-width (64-d) table in smem (128 KB), pre-converted once per launch.
//  - grid = 256 CTAs x 512 thr; 512 pixels per CTA, no D split.
//  - Phase 1 (thread-per-pixel): fern logic -> 8 packed (coeff, byte-offset) uint2 in smem.
//  - Phase 2: LDS.128 gathers (8 halfs/lane, 8 lanes/pixel, 4 pixels/instr),
//    params via broadcast LDS.64. fp32 accumulation in 64 regs/lane.
//  - Epilogue: stride-65 smem transpose -> fully coalesced STG.

#define TPB 512
#define PX  512
#define TAB_BYTES 131072            // 1024 rows * 64 halfs * 2B (row = 128B)
#define PAR_STRIDE 72               // 8 probes * 8B + 8B pad (bank decorrelation)
#define SMEM_BYTES (TAB_BYTES + PX * PAR_STRIDE)   // 167936

__device__ __half g_W16[16 * 1024 * 64];

__global__ void cvt_kernel(const float4* __restrict__ W)
{
    int i = blockIdx.x * blockDim.x + threadIdx.x;   // 262144 float4
    float4 v = W[i];
    __half2 a = __floats2half2_rn(v.x, v.y);
    __half2 b = __floats2half2_rn(v.z, v.w);
    uint2 r;
    r.x = *reinterpret_cast<unsigned*>(&a);
    r.y = *reinterpret_cast<unsigned*>(&b);
    reinterpret_cast<uint2*>(g_W16)[i] = r;
}

extern __shared__ char smem_raw[];

__global__ __launch_bounds__(TPB, 1)
void fern_kernel(const float* __restrict__ B,
                 const float* __restrict__ bias,
                 float* __restrict__ out)
{
    __half* s_tab = (__half*)smem_raw;
    char*   s_par = smem_raw + TAB_BYTES;
    float*  s_out = (float*)smem_raw;        // epilogue reuse (512 x 65 floats = 133 KB)

    const int tid  = threadIdx.x;
    const int lane = tid & 31;
    const int warp = tid >> 5;
    const int pxbase = blockIdx.x * PX;
    const int n      = pxbase >> 12;         // 4096 px per image
    const int hwbase = pxbase & 4095;

    const float* Bb = B + (n * 160) * 4096 + (hwbase + tid);

    float acc[64];
    #pragma unroll
    for (int i = 0; i < 64; ++i) acc[i] = 0.f;

    // lane's fixed 16-byte d-slice within a 128B table row
    const char* gl = (const char*)s_tab + (lane & 7) * 16;
    // lane's pixel-within-group offset
    const int px_sub = lane >> 3;            // 0..3

    #pragma unroll 1
    for (int m = 0; m < 16; ++m) {
        __syncthreads();   // previous fern's phase 2 done

        // ---- fill fp16 table: 8192 uint4 = 128 KB, coalesced L2 reads ----
        {
            const uint4* src = (const uint4*)(g_W16 + m * 65536);
            uint4* dst = (uint4*)s_tab;
            #pragma unroll
            for (int i = 0; i < 16; ++i)
                dst[tid + i * TPB] = src[tid + i * TPB];
        }

        // ---- phase 1: per-thread fern logic ----
        float t[10];
        #pragma unroll
        for (int k = 0; k < 10; ++k)
            t[k] = Bb[(m * 10 + k) * 4096];

        int wb = 0;
        float bsp = 1.f;
        float ba[10];
        #pragma unroll
        for (int k = 0; k < 10; ++k) {
            if (t[k] >= 0.5f) wb |= (1 << k);
            bsp *= fmaxf(t[k], 1.f - t[k]);
            ba[k] = fabsf(t[k] - 0.5f);
        }

        int abi0, abi1, abi2;
        float av0, av1, av2;
        {
            float best = ba[0]; int bi = 0; float bt = t[0];
            #pragma unroll
            for (int k = 1; k < 10; ++k)
                if (ba[k] < best) { best = ba[k]; bi = k; bt = t[k]; }
            abi0 = bi; av0 = bt;
        }
        {
            float best = 3.0e38f; int bi = 0; float bt = 0.f;
            #pragma unroll
            for (int k = 0; k < 10; ++k)
                if (k != abi0 && ba[k] < best) { best = ba[k]; bi = k; bt = t[k]; }
            abi1 = bi; av1 = bt;
        }
        {
            float best = 3.0e38f; int bi = 0; float bt = 0.f;
            #pragma unroll
            for (int k = 0; k < 10; ++k)
                if (k != abi0 && k != abi1 && ba[k] < best) { best = ba[k]; bi = k; bt = t[k]; }
            abi2 = bi; av2 = bt;
        }

        const float d0 = 1.f - av0, d1 = 1.f - av1, d2 = 1.f - av2;
        const float denom = fmaxf(av0, d0) * fmaxf(av1, d1) * fmaxf(av2, d2);
        const float bspp = bsp / denom;

        float cp[8];
        {
            float g0 = bspp * d0,  g1 = bspp * av0;
            float c00 = g0 * d1,  c10 = g1 * d1;
            float c01 = g0 * av1, c11 = g1 * av1;
            cp[0] = c00 * d2;  cp[1] = c10 * d2;  cp[2] = c01 * d2;  cp[3] = c11 * d2;
            cp[4] = c00 * av2; cp[5] = c10 * av2; cp[6] = c01 * av2; cp[7] = c11 * av2;
        }
        int io[8];
        {
            const int m0 = 1 << abi0, m1 = 1 << abi1, m2 = 1 << abi2;
            const int b0 = wb & ~(m0 | m1 | m2);
            const int i0 = b0, i1 = b0 | m0, i2 = b0 | m1, i3 = b0 | m0 | m1;
            io[0] = i0 << 7;        io[1] = i1 << 7;       // row byte offset (128B rows)
            io[2] = i2 << 7;        io[3] = i3 << 7;
            io[4] = (i0 | m2) << 7; io[5] = (i1 | m2) << 7;
            io[6] = (i2 | m2) << 7; io[7] = (i3 | m2) << 7;
        }

        // write packed params (STS.64, conflict-free: 72B px stride)
        {
            char* myp = s_par + tid * PAR_STRIDE;
            #pragma unroll
            for (int j = 0; j < 8; ++j) {
                uint2 v;
                v.x = __float_as_uint(cp[j]);
                v.y = (unsigned)io[j];
                *(uint2*)(myp + j * 8) = v;
            }
        }
        __syncthreads();

        // ---- phase 2: vectorized gathers, 4 px per instruction ----
        #pragma unroll
        for (int g = 0; g < 8; ++g) {
            const char* pp = s_par + (warp * 32 + g * 4 + px_sub) * PAR_STRIDE;
            float a0 = acc[g*8+0], a1 = acc[g*8+1], a2 = acc[g*8+2], a3 = acc[g*8+3];
            float a4 = acc[g*8+4], a5 = acc[g*8+5], a6 = acc[g*8+6], a7 = acc[g*8+7];
            #pragma unroll
            for (int j = 0; j < 8; ++j) {
                uint2 pr = *(const uint2*)(pp + j * 8);        // broadcast LDS.64
                float c  = __uint_as_float(pr.x);
                uint4 w4 = *(const uint4*)(gl + pr.y);         // LDS.128 gather
                float2 f0 = __half22float2(*reinterpret_cast<__half2*>(&w4.x));
                float2 f1 = __half22float2(*reinterpret_cast<__half2*>(&w4.y));
                float2 f2 = __half22float2(*reinterpret_cast<__half2*>(&w4.z));
                float2 f3 = __half22float2(*reinterpret_cast<__half2*>(&w4.w));
                a0 = fmaf(c, f0.x, a0); a1 = fmaf(c, f0.y, a1);
                a2 = fmaf(c, f1.x, a2); a3 = fmaf(c, f1.y, a3);
                a4 = fmaf(c, f2.x, a4); a5 = fmaf(c, f2.y, a5);
                a6 = fmaf(c, f3.x, a6); a7 = fmaf(c, f3.y, a7);
            }
            acc[g*8+0] = a0; acc[g*8+1] = a1; acc[g*8+2] = a2; acc[g*8+3] = a3;
            acc[g*8+4] = a4; acc[g*8+5] = a5; acc[g*8+6] = a6; acc[g*8+7] = a7;
        }
    }

    // ---- epilogue: stride-65 transpose (conflict-free both directions) ----
    __syncthreads();
    #pragma unroll
    for (int g = 0; g < 8; ++g) {
        int px = warp * 32 + g * 4 + px_sub;
        float* row = s_out + px * 65 + (lane & 7) * 8;
        #pragma unroll
        for (int r = 0; r < 8; ++r) row[r] = acc[g * 8 + r];
    }
    __syncthreads();

    {
        const float* srow = s_out + tid * 65;
        float* obase = out + (n * 64) * 4096 + hwbase + tid;
        #pragma unroll
        for (int d = 0; d < 64; ++d)
            obase[d * 4096] = srow[d] + bias[d];
    }
}

extern "C" void kernel_launch(void* const* d_in, const int* in_sizes, int n_in,
                              void* d_out, int out_size)
{
    const float* B    = (const float*)d_in[0];
    const float* W    = (const float*)d_in[1];
    const float* bias = (const float*)d_in[2];
    float* out = (float*)d_out;

    cvt_kernel<<<1024, 256>>>((const float4*)W);

    cudaFuncSetAttribute(fern_kernel, cudaFuncAttributeMaxDynamicSharedMemorySize, SMEM_BYTES);
    fern_kernel<<<256, TPB, SMEM_BYTES>>>(B, bias, out);
}

// round 4
// speedup vs baseline: 3.3624x; 1.2133x over previous
#include <cuda_runtime.h>
#include <cuda_fp16.h>

// FernSparseTable v3:
//  - fp16 table (128 KB smem) filled via cp.async.bulk + mbarrier, overlapped with phase 1.
//  - Phase 1: thread-per-pixel fern logic -> 8 packed (half2 coeff, byte-offset) params.
//  - Phase 2: LDS.128 param reads (2 probes/load), LDS.128 gathers (4 px/instr),
//    HFMA2 accumulation per fern, fp32 flush per fern into 64 master accumulators.
//  - Epilogue: stride-65 smem transpose -> coalesced STG.

#define TPB 512
#define PX  512
#define TAB_BYTES 131072            // 1024 rows * 128 B
#define PAR_STRIDE 80               // 8 probes * 8B + 16B pad (quad decorrelation)
#define PAR_BYTES (PX * PAR_STRIDE) // 40960
#define MBAR_OFF  (TAB_BYTES + PAR_BYTES)
#define SMEM_BYTES (MBAR_OFF + 16)  // 172048

__device__ __align__(128) __half g_W16[16 * 1024 * 64];

__global__ void cvt_kernel(const float4* __restrict__ W)
{
    int i = blockIdx.x * blockDim.x + threadIdx.x;   // 262144 float4
    float4 v = W[i];
    __half2 a = __floats2half2_rn(v.x, v.y);
    __half2 b = __floats2half2_rn(v.z, v.w);
    uint2 r;
    r.x = *reinterpret_cast<unsigned*>(&a);
    r.y = *reinterpret_cast<unsigned*>(&b);
    reinterpret_cast<uint2*>(g_W16)[i] = r;
}

__device__ __forceinline__ __half2 u2h2(unsigned u) {
    return *reinterpret_cast<__half2*>(&u);
}

extern __shared__ char smem_raw[];

__global__ __launch_bounds__(TPB, 1)
void fern_kernel(const float* __restrict__ B,
                 const float* __restrict__ bias,
                 float* __restrict__ out)
{
    char*   s_tab = smem_raw;
    char*   s_par = smem_raw + TAB_BYTES;
    float*  s_out = (float*)smem_raw;        // epilogue reuse (512 x 65 floats)

    const int tid  = threadIdx.x;
    const int lane = tid & 31;
    const int warp = tid >> 5;
    const int pxbase = blockIdx.x * PX;
    const int n      = pxbase >> 12;
    const int hwbase = pxbase & 4095;

    unsigned smem_u32;
    {
        unsigned long long tmp = __cvta_generic_to_shared(smem_raw);
        smem_u32 = (unsigned)tmp;
    }
    const unsigned mbar = smem_u32 + MBAR_OFF;

    if (tid == 0) {
        asm volatile("mbarrier.init.shared.b64 [%0], 1;" :: "r"(mbar) : "memory");
        asm volatile("fence.proxy.async.shared::cta;" ::: "memory");
    }

    const float* Bb = B + (n * 160) * 4096 + (hwbase + tid);

    float acc[64];
    #pragma unroll
    for (int i = 0; i < 64; ++i) acc[i] = 0.f;

    const char* gl = s_tab + (lane & 7) * 16;   // lane's 16B d-slice in a row
    const int px_sub = lane >> 3;               // 0..3

    const unsigned long long Wg =
        (unsigned long long)__cvta_generic_to_global(g_W16);

    #pragma unroll 1
    for (int m = 0; m < 16; ++m) {
        __syncthreads();   // prev fern's gathers + param reads done; mbar init visible (m=0)

        // ---- issue async bulk fill of fern m's table (overlaps with phase 1) ----
        if (tid == 0) {
            asm volatile("mbarrier.arrive.expect_tx.shared.b64 _, [%0], %1;"
                         :: "r"(mbar), "r"(TAB_BYTES) : "memory");
            unsigned long long src = Wg + (unsigned long long)m * 131072ull;
            #pragma unroll
            for (int c = 0; c < 4; ++c) {
                asm volatile(
                    "cp.async.bulk.shared::cta.global.mbarrier::complete_tx::bytes "
                    "[%0], [%1], %2, [%3];"
                    :: "r"(smem_u32 + c * 32768), "l"(src + c * 32768ull),
                       "r"(32768), "r"(mbar) : "memory");
            }
        }

        // ---- phase 1: per-thread fern logic ----
        float t[10];
        #pragma unroll
        for (int k = 0; k < 10; ++k)
            t[k] = Bb[(m * 10 + k) * 4096];

        int wb = 0;
        float bsp = 1.f;
        float ba[10];
        #pragma unroll
        for (int k = 0; k < 10; ++k) {
            if (t[k] >= 0.5f) wb |= (1 << k);
            bsp *= fmaxf(t[k], 1.f - t[k]);
            ba[k] = fabsf(t[k] - 0.5f);
        }

        int abi0, abi1, abi2;
        float av0, av1, av2;
        {
            float best = ba[0]; int bi = 0; float bt = t[0];
            #pragma unroll
            for (int k = 1; k < 10; ++k)
                if (ba[k] < best) { best = ba[k]; bi = k; bt = t[k]; }
            abi0 = bi; av0 = bt;
        }
        {
            float best = 3.0e38f; int bi = 0; float bt = 0.f;
            #pragma unroll
            for (int k = 0; k < 10; ++k)
                if (k != abi0 && ba[k] < best) { best = ba[k]; bi = k; bt = t[k]; }
            abi1 = bi; av1 = bt;
        }
        {
            float best = 3.0e38f; int bi = 0; float bt = 0.f;
            #pragma unroll
            for (int k = 0; k < 10; ++k)
                if (k != abi0 && k != abi1 && ba[k] < best) { best = ba[k]; bi = k; bt = t[k]; }
            abi2 = bi; av2 = bt;
        }

        const float d0 = 1.f - av0, d1 = 1.f - av1, d2 = 1.f - av2;
        const float denom = fmaxf(av0, d0) * fmaxf(av1, d1) * fmaxf(av2, d2);
        const float bspp = bsp / denom;

        float cp[8];
        {
            float g0 = bspp * d0,  g1 = bspp * av0;
            float c00 = g0 * d1,  c10 = g1 * d1;
            float c01 = g0 * av1, c11 = g1 * av1;
            cp[0] = c00 * d2;  cp[1] = c10 * d2;  cp[2] = c01 * d2;  cp[3] = c11 * d2;
            cp[4] = c00 * av2; cp[5] = c10 * av2; cp[6] = c01 * av2; cp[7] = c11 * av2;
        }
        unsigned ch[8];
        #pragma unroll
        for (int j = 0; j < 8; ++j) {
            __half2 h = __floats2half2_rn(cp[j], cp[j]);
            ch[j] = *reinterpret_cast<unsigned*>(&h);
        }
        int io[8];
        {
            const int m0 = 1 << abi0, m1 = 1 << abi1, m2 = 1 << abi2;
            const int b0 = wb & ~(m0 | m1 | m2);
            const int i0 = b0, i1 = b0 | m0, i2 = b0 | m1, i3 = b0 | m0 | m1;
            io[0] = i0 << 7;        io[1] = i1 << 7;
            io[2] = i2 << 7;        io[3] = i3 << 7;
            io[4] = (i0 | m2) << 7; io[5] = (i1 | m2) << 7;
            io[6] = (i2 | m2) << 7; io[7] = (i3 | m2) << 7;
        }

        // write packed params: 4 x STS.128, 2 probes per uint4
        {
            uint4* myp = (uint4*)(s_par + tid * PAR_STRIDE);
            #pragma unroll
            for (int jj = 0; jj < 4; ++jj)
                myp[jj] = make_uint4(ch[2*jj], (unsigned)io[2*jj],
                                     ch[2*jj+1], (unsigned)io[2*jj+1]);
        }
        __syncwarp();   // phase 2 reads only this warp's params

        // wait for table fill
        {
            const unsigned parity = m & 1u;
            unsigned done;
            asm volatile(
                "{\n\t.reg .pred p;\n\t"
                "mbarrier.try_wait.parity.acquire.cta.shared::cta.b64 p, [%1], %2;\n\t"
                "selp.b32 %0, 1, 0, p;\n\t}"
                : "=r"(done) : "r"(mbar), "r"(parity) : "memory");
            if (!done) {
                asm volatile(
                    "{\n\t.reg .pred P1;\n\t"
                    "WL_%=:\n\t"
                    "mbarrier.try_wait.parity.acquire.cta.shared::cta.b64 P1, [%0], %1, 0x989680;\n\t"
                    "@P1 bra.uni WD_%=;\n\t"
                    "bra.uni WL_%=;\n\t"
                    "WD_%=:\n\t}"
                    :: "r"(mbar), "r"(parity) : "memory");
            }
        }

        // ---- phase 2: HFMA2 gathers, 4 px per instruction ----
        #pragma unroll
        for (int g = 0; g < 8; ++g) {
            const uint4* pp = (const uint4*)(s_par + (warp * 32 + g * 4 + px_sub) * PAR_STRIDE);
            __half2 h0 = __floats2half2_rn(0.f, 0.f);
            __half2 h1 = h0, h2 = h0, h3 = h0;
            #pragma unroll
            for (int jj = 0; jj < 4; ++jj) {
                uint4 pr = pp[jj];
                {
                    __half2 c = u2h2(pr.x);
                    uint4 w4 = *(const uint4*)(gl + pr.y);
                    h0 = __hfma2(c, u2h2(w4.x), h0);
                    h1 = __hfma2(c, u2h2(w4.y), h1);
                    h2 = __hfma2(c, u2h2(w4.z), h2);
                    h3 = __hfma2(c, u2h2(w4.w), h3);
                }
                {
                    __half2 c = u2h2(pr.z);
                    uint4 w4 = *(const uint4*)(gl + pr.w);
                    h0 = __hfma2(c, u2h2(w4.x), h0);
                    h1 = __hfma2(c, u2h2(w4.y), h1);
                    h2 = __hfma2(c, u2h2(w4.z), h2);
                    h3 = __hfma2(c, u2h2(w4.w), h3);
                }
            }
            float2 f0 = __half22float2(h0);
            float2 f1 = __half22float2(h1);
            float2 f2 = __half22float2(h2);
            float2 f3 = __half22float2(h3);
            acc[g*8+0] += f0.x; acc[g*8+1] += f0.y;
            acc[g*8+2] += f1.x; acc[g*8+3] += f1.y;
            acc[g*8+4] += f2.x; acc[g*8+5] += f2.y;
            acc[g*8+6] += f3.x; acc[g*8+7] += f3.y;
        }
    }

    // ---- epilogue: stride-65 transpose -> coalesced stores ----
    __syncthreads();
    #pragma unroll
    for (int g = 0; g < 8; ++g) {
        int px = warp * 32 + g * 4 + px_sub;
        float* row = s_out + px * 65 + (lane & 7) * 8;
        #pragma unroll
        for (int r = 0; r < 8; ++r) row[r] = acc[g * 8 + r];
    }
    __syncthreads();

    {
        const float* srow = s_out + tid * 65;
        float* obase = out + (n * 64) * 4096 + hwbase + tid;
        #pragma unroll
        for (int d = 0; d < 64; ++d)
            obase[d * 4096] = srow[d] + bias[d];
    }
}

extern "C" void kernel_launch(void* const* d_in, const int* in_sizes, int n_in,
                              void* d_out, int out_size)
{
    const float* B    = (const float*)d_in[0];
    const float* W    = (const float*)d_in[1];
    const float* bias = (const float*)d_in[2];
    float* out = (float*)d_out;

    cvt_kernel<<<1024, 256>>>((const float4*)W);

    cudaFuncSetAttribute(fern_kernel, cudaFuncAttributeMaxDynamicSharedMemorySize, SMEM_BYTES);
    fern_kernel<<<256, TPB, SMEM_BYTES>>>(B, bias, out);
}